// round 3
// baseline (speedup 1.0000x reference)
#include <cuda_runtime.h>
#include <cstddef>

#define BB 2048
#define TT 1024
#define DD 64
#define HH 32

typedef unsigned long long u64;

// ---- packed fp32x2 helpers (sm_100+) ----
__device__ __forceinline__ u64 ffma2(u64 a, u64 b, u64 c) {
    u64 d;
    asm("fma.rn.f32x2 %0, %1, %2, %3;" : "=l"(d) : "l"(a), "l"(b), "l"(c));
    return d;
}
__device__ __forceinline__ u64 pack2(float lo, float hi) {
    u64 r;
    asm("mov.b64 %0, {%1, %2};" : "=l"(r) : "f"(lo), "f"(hi));
    return r;
}
__device__ __forceinline__ float sum2(u64 v) {
    float a, b;
    asm("mov.b64 {%0, %1}, %2;" : "=f"(a), "=f"(b) : "l"(v));
    return a + b;
}
// sigmoid via ex2.approx + rcp.approx (rel err ~1e-6; safe through recurrence)
__device__ __forceinline__ float fast_sigmoid(float x) {
    float e;
    asm("ex2.approx.f32 %0, %1;" : "=f"(e) : "f"(-1.4426950408889634f * x));
    float r;
    asm("rcp.approx.f32 %0, %1;" : "=f"(r) : "f"(1.0f + e));
    return r;
}
__device__ __forceinline__ float fast_tanh(float x) {
    return fmaf(2.0f, fast_sigmoid(2.0f * x), -1.0f);
}

// K=32 gemm: for 4 rows, 3 gates per lane. w4 layout: [kk<8][gate<96] float4.
// in4: [row<4][kk<8] float4 (broadcast reads). Accumulators are f32x2 (K-paired).
__device__ __forceinline__ void mm32(const float4* __restrict__ w4,
                                     const float4* __restrict__ in4,
                                     int lane, u64* ar, u64* az, u64* an) {
#pragma unroll 4
    for (int kk = 0; kk < 8; kk++) {
        ulonglong2 wr = *(const ulonglong2*)(w4 + kk * 96 + lane);
        ulonglong2 wz = *(const ulonglong2*)(w4 + kk * 96 + 32 + lane);
        ulonglong2 wn = *(const ulonglong2*)(w4 + kk * 96 + 64 + lane);
#pragma unroll
        for (int r = 0; r < 4; r++) {
            ulonglong2 hv = *(const ulonglong2*)(in4 + r * 8 + kk);
            ar[r] = ffma2(wr.x, hv.x, ar[r]);
            ar[r] = ffma2(wr.y, hv.y, ar[r]);
            az[r] = ffma2(wz.x, hv.x, az[r]);
            az[r] = ffma2(wz.y, hv.y, az[r]);
            an[r] = ffma2(wn.x, hv.x, an[r]);
            an[r] = ffma2(wn.y, hv.y, an[r]);
        }
    }
}

__global__ void __launch_bounds__(128, 1)
gru2_kernel(const float* __restrict__ x,
            const float* __restrict__ wih0, const float* __restrict__ whh0,
            const float* __restrict__ bih0, const float* __restrict__ bhh0,
            const float* __restrict__ wih1, const float* __restrict__ whh1,
            const float* __restrict__ bih1, const float* __restrict__ bhh1,
            const float* __restrict__ wcls, const float* __restrict__ bcls,
            float* __restrict__ out)
{
    extern __shared__ float4 sm[];
    float4* w4ih0 = sm;                 // [16][96]  (K=64 input gemm, layer 0)
    float4* w4hh0 = w4ih0 + 16 * 96;    // [8][96]
    float4* w4ih1 = w4hh0 + 8 * 96;     // [8][96]
    float4* w4hh1 = w4ih1 + 8 * 96;     // [8][96]
    float4* xs    = w4hh1 + 8 * 96;     // [4 warps][4 rows][16]
    float4* hs0   = xs + 4 * 64;        // [4 warps][4 rows][8]
    float4* hs1   = hs0 + 4 * 32;       // [4 warps][4 rows][8]

    const int tid  = threadIdx.x;
    const int warp = tid >> 5;
    const int lane = tid & 31;

    // Cooperative weight transpose into shared: w4[kk][g] = W[g][4kk..4kk+3]
    for (int idx = tid; idx < 96 * 16; idx += 128) {
        int g = idx % 96, kk = idx / 96;
        w4ih0[kk * 96 + g] = *(const float4*)(wih0 + g * 64 + kk * 4);
    }
    for (int idx = tid; idx < 96 * 8; idx += 128) {
        int g = idx % 96, kk = idx / 96;
        w4hh0[kk * 96 + g] = *(const float4*)(whh0 + g * 32 + kk * 4);
        w4ih1[kk * 96 + g] = *(const float4*)(wih1 + g * 32 + kk * 4);
        w4hh1[kk * 96 + g] = *(const float4*)(whh1 + g * 32 + kk * 4);
    }

    const int rowbase = blockIdx.x * 16 + warp * 4;

    // Biases in registers (lane j owns gates j, 32+j, 64+j)
    const float br0i = bih0[lane], bz0i = bih0[32 + lane], bn0i = bih0[64 + lane];
    const float br0h = bhh0[lane], bz0h = bhh0[32 + lane], bn0h = bhh0[64 + lane];
    const float br1i = bih1[lane], bz1i = bih1[32 + lane], bn1i = bih1[64 + lane];
    const float br1h = bhh1[lane], bz1h = bhh1[32 + lane], bn1h = bhh1[64 + lane];
    const float wc = wcls[lane];
    const float bc = bcls[0];

    float h0r[4] = {0.f, 0.f, 0.f, 0.f};
    float h1r[4] = {0.f, 0.f, 0.f, 0.f};

    float* hs0f = (float*)(hs0 + warp * 32);
    float* hs1f = (float*)(hs1 + warp * 32);
    const float4* h04 = hs0 + warp * 32;
    const float4* h14 = hs1 + warp * 32;
#pragma unroll
    for (int r = 0; r < 4; r++) { hs0f[r * 32 + lane] = 0.f; hs1f[r * 32 + lane] = 0.f; }

    // x staging: each lane loads 2 float4/step (slots lane, lane+32).
    float4* xsw = xs + warp * 64;
    const int s1 = lane + 32;
    const float4* xp0 = (const float4*)(x + (size_t)(rowbase + (lane >> 4)) * TT * DD) + (lane & 15);
    const float4* xp1 = (const float4*)(x + (size_t)(rowbase + (s1 >> 4)) * TT * DD) + (s1 & 15);
    float4* xst0 = xsw + lane;
    float4* xst1 = xsw + s1;

    __syncthreads();

    float4 xb0 = *xp0, xb1 = *xp1;     // prefetch t=0
    xp0 += 16; xp1 += 16;

    for (int t = 0; t < TT; t++) {
        *xst0 = xb0;
        *xst1 = xb1;
        __syncwarp();
        if (t + 1 < TT) {              // prefetch next step while computing
            xb0 = *xp0; xb1 = *xp1;
            xp0 += 16; xp1 += 16;
        }

        // ---- layer 0: input gemm (K=64) ----
        u64 ar[4], az[4], an[4];
#pragma unroll
        for (int r = 0; r < 4; r++) {
            ar[r] = pack2(br0i, 0.f); az[r] = pack2(bz0i, 0.f); an[r] = pack2(bn0i, 0.f);
        }
#pragma unroll 4
        for (int kk = 0; kk < 16; kk++) {
            ulonglong2 wr = *(const ulonglong2*)(w4ih0 + kk * 96 + lane);
            ulonglong2 wz = *(const ulonglong2*)(w4ih0 + kk * 96 + 32 + lane);
            ulonglong2 wn = *(const ulonglong2*)(w4ih0 + kk * 96 + 64 + lane);
#pragma unroll
            for (int r = 0; r < 4; r++) {
                ulonglong2 xv = *(const ulonglong2*)(xsw + r * 16 + kk);
                ar[r] = ffma2(wr.x, xv.x, ar[r]); ar[r] = ffma2(wr.y, xv.y, ar[r]);
                az[r] = ffma2(wz.x, xv.x, az[r]); az[r] = ffma2(wz.y, xv.y, az[r]);
                an[r] = ffma2(wn.x, xv.x, an[r]); an[r] = ffma2(wn.y, xv.y, an[r]);
            }
        }
        float xr[4], xz[4], xn[4];
#pragma unroll
        for (int r = 0; r < 4; r++) { xr[r] = sum2(ar[r]); xz[r] = sum2(az[r]); xn[r] = sum2(an[r]); }

        // ---- layer 0: hidden gemm (K=32, reads old h0) ----
        u64 gr[4], gz[4], gn[4];
#pragma unroll
        for (int r = 0; r < 4; r++) {
            gr[r] = pack2(br0h, 0.f); gz[r] = pack2(bz0h, 0.f); gn[r] = pack2(bn0h, 0.f);
        }
        mm32(w4hh0, h04, lane, gr, gz, gn);

#pragma unroll
        for (int r = 0; r < 4; r++) {
            float rg = fast_sigmoid(xr[r] + sum2(gr[r]));
            float zg = fast_sigmoid(xz[r] + sum2(gz[r]));
            float ng = fast_tanh(xn[r] + rg * sum2(gn[r]));   // b_hh_n inside r* (torch GRU)
            h0r[r] = ng + zg * (h0r[r] - ng);                 // (1-z)n + z h
        }
        __syncwarp();                                          // gh0 reads done before overwrite
#pragma unroll
        for (int r = 0; r < 4; r++) hs0f[r * 32 + lane] = h0r[r];
        __syncwarp();

        // ---- layer 1: input gemm (K=32, reads new h0) ----
        u64 cr[4], cz[4], cn[4];
#pragma unroll
        for (int r = 0; r < 4; r++) {
            cr[r] = pack2(br1i, 0.f); cz[r] = pack2(bz1i, 0.f); cn[r] = pack2(bn1i, 0.f);
        }
        mm32(w4ih1, h04, lane, cr, cz, cn);

        // ---- layer 1: hidden gemm (K=32, reads old h1) ----
        u64 dr[4], dz[4], dn[4];
#pragma unroll
        for (int r = 0; r < 4; r++) {
            dr[r] = pack2(br1h, 0.f); dz[r] = pack2(bz1h, 0.f); dn[r] = pack2(bn1h, 0.f);
        }
        mm32(w4hh1, h14, lane, dr, dz, dn);

#pragma unroll
        for (int r = 0; r < 4; r++) {
            float rg = fast_sigmoid(sum2(cr[r]) + sum2(dr[r]));
            float zg = fast_sigmoid(sum2(cz[r]) + sum2(dz[r]));
            float ng = fast_tanh(sum2(cn[r]) + rg * sum2(dn[r]));
            h1r[r] = ng + zg * (h1r[r] - ng);
        }
        __syncwarp();                                          // gh1 reads done before overwrite
#pragma unroll
        for (int r = 0; r < 4; r++) hs1f[r * 32 + lane] = h1r[r];
        __syncwarp();
    }

    // ---- outputs: y [B], hidden [2,B,H] ----
#pragma unroll
    for (int r = 0; r < 4; r++) {
        int row = rowbase + r;
        out[BB + row * HH + lane] = h0r[r];
        out[BB + BB * HH + row * HH + lane] = h1r[r];
        float p = h1r[r] * wc;
#pragma unroll
        for (int off = 16; off; off >>= 1) p += __shfl_xor_sync(0xffffffffu, p, off);
        if (lane == 0) out[row] = fast_sigmoid(p + bc);
    }
}

extern "C" void kernel_launch(void* const* d_in, const int* in_sizes, int n_in,
                              void* d_out, int out_size) {
    (void)in_sizes; (void)n_in; (void)out_size;
    const float* x    = (const float*)d_in[0];
    const float* wih0 = (const float*)d_in[1];
    const float* whh0 = (const float*)d_in[2];
    const float* bih0 = (const float*)d_in[3];
    const float* bhh0 = (const float*)d_in[4];
    const float* wih1 = (const float*)d_in[5];
    const float* whh1 = (const float*)d_in[6];
    const float* bih1 = (const float*)d_in[7];
    const float* bhh1 = (const float*)d_in[8];
    const float* wcls = (const float*)d_in[9];
    const float* bcls = (const float*)d_in[10];
    float* out = (float*)d_out;

    const int smem_bytes = 4352 * 16;  // 69,632 B dynamic shared
    cudaFuncSetAttribute(gru2_kernel, cudaFuncAttributeMaxDynamicSharedMemorySize, smem_bytes);
    gru2_kernel<<<128, 128, smem_bytes>>>(x, wih0, whh0, bih0, bhh0,
                                          wih1, whh1, bih1, bhh1, wcls, bcls, out);
}

// round 4
// speedup vs baseline: 1.1955x; 1.1955x over previous
#include <cuda_runtime.h>
#include <cstddef>

#define BB 2048
#define TT 1024
#define DD 64
#define HH 32

typedef unsigned long long u64;

// ---- packed fp32x2 helpers (sm_100+) ----
__device__ __forceinline__ u64 ffma2(u64 a, u64 b, u64 c) {
    u64 d;
    asm("fma.rn.f32x2 %0, %1, %2, %3;" : "=l"(d) : "l"(a), "l"(b), "l"(c));
    return d;
}
__device__ __forceinline__ u64 pack2(float lo, float hi) {
    u64 r;
    asm("mov.b64 %0, {%1, %2};" : "=l"(r) : "f"(lo), "f"(hi));
    return r;
}
__device__ __forceinline__ float sum2(u64 v) {
    float a, b;
    asm("mov.b64 {%0, %1}, %2;" : "=f"(a), "=f"(b) : "l"(v));
    return a + b;
}
__device__ __forceinline__ float fast_sigmoid(float x) {
    float e;
    asm("ex2.approx.f32 %0, %1;" : "=f"(e) : "f"(-1.4426950408889634f * x));
    float r;
    asm("rcp.approx.f32 %0, %1;" : "=f"(r) : "f"(1.0f + e));
    return r;
}
__device__ __forceinline__ float fast_tanh(float x) {
    return fmaf(2.0f, fast_sigmoid(2.0f * x), -1.0f);
}

// full-block barrier, callable from divergent (per-warp-converged) code paths;
// producer and consumer loops execute the SAME count of these.
#define BAR_ALL() asm volatile("bar.sync 0, 256;" ::: "memory")

__global__ void __launch_bounds__(256, 1)
gru2_kernel(const float* __restrict__ x,
            const float* __restrict__ wih0, const float* __restrict__ whh0,
            const float* __restrict__ bih0, const float* __restrict__ bhh0,
            const float* __restrict__ wih1, const float* __restrict__ whh1,
            const float* __restrict__ bih1, const float* __restrict__ bhh1,
            const float* __restrict__ wcls, const float* __restrict__ bcls,
            float* __restrict__ out)
{
    extern __shared__ float4 sm[];
    float4* w4ih1 = sm;                      // [8][96] float4
    float4* w4hh1 = w4ih1 + 768;             // [8][96]
    float*  gxs   = (float*)(w4hh1 + 768);   // [2 slots][2 K-halves][16 rows][96]
    float4* hs0   = (float4*)(gxs + 6144);   // [4 cwarps][4 rows][8]
    float4* hs1   = hs0 + 128;
    float4* xs    = hs1 + 128;               // [4 pwarps][8 rows][8]

    const int tid  = threadIdx.x;
    const int warp = tid >> 5;
    const int lane = tid & 31;
    const int rowbase16 = blockIdx.x * 16;

    // cooperative transpose of layer-1 weights into shared: [kk][gate] float4
    for (int idx = tid; idx < 768; idx += 256) {
        int g = idx % 96, kk = idx / 96;
        w4ih1[kk * 96 + g] = *(const float4*)(wih1 + g * 32 + kk * 4);
        w4hh1[kk * 96 + g] = *(const float4*)(whh1 + g * 32 + kk * 4);
    }

    if (warp < 4) {
        // ================= consumer: recurrence for rows rowbase16+4w..+3 =================
        // W_hh0 fully register-resident: lane j holds rows j, 32+j, 64+j (f32x2 packed)
        u64 cwr[16], cwz[16], cwn[16];
#pragma unroll
        for (int i = 0; i < 8; i++) {
            ulonglong2 a = *(const ulonglong2*)(whh0 + lane * 32 + i * 4);
            ulonglong2 b = *(const ulonglong2*)(whh0 + (32 + lane) * 32 + i * 4);
            ulonglong2 c = *(const ulonglong2*)(whh0 + (64 + lane) * 32 + i * 4);
            cwr[2 * i] = a.x; cwr[2 * i + 1] = a.y;
            cwz[2 * i] = b.x; cwz[2 * i + 1] = b.y;
            cwn[2 * i] = c.x; cwn[2 * i + 1] = c.y;
        }
        const float br0h = bhh0[lane], bz0h = bhh0[32 + lane], bn0h = bhh0[64 + lane];
        const float br1i = bih1[lane], bz1i = bih1[32 + lane], bn1i = bih1[64 + lane];
        const float br1h = bhh1[lane], bz1h = bhh1[32 + lane], bn1h = bhh1[64 + lane];
        const float wc = wcls[lane];
        const float bc = bcls[0];

        float h0r[4] = {0.f, 0.f, 0.f, 0.f};
        float h1r[4] = {0.f, 0.f, 0.f, 0.f};
        float* hs0f = (float*)(hs0 + warp * 32);
        float* hs1f = (float*)(hs1 + warp * 32);
        const float4* h04 = hs0 + warp * 32;
        const float4* h14 = hs1 + warp * 32;
#pragma unroll
        for (int r = 0; r < 4; r++) { hs0f[r * 32 + lane] = 0.f; hs1f[r * 32 + lane] = 0.f; }

        const float* gxw = gxs + (warp * 4) * 96;   // + slot*3072 + half*1536 + r*96

        for (int t = 0; t < TT; t++) {
            BAR_ALL();                              // slot t&1 now full
            const float* g0 = gxw + (t & 1) * 3072;
            const float* g1 = g0 + 1536;

            // ---- layer 0: hidden gemm from register weights ----
            u64 gr[4], gz[4], gn[4];
#pragma unroll
            for (int r = 0; r < 4; r++) {
                gr[r] = pack2(br0h, 0.f); gz[r] = pack2(bz0h, 0.f); gn[r] = pack2(bn0h, 0.f);
            }
#pragma unroll
            for (int kk = 0; kk < 8; kk++) {
#pragma unroll
                for (int r = 0; r < 4; r++) {
                    ulonglong2 hv = *(const ulonglong2*)(h04 + r * 8 + kk);
                    gr[r] = ffma2(cwr[2 * kk], hv.x, gr[r]); gr[r] = ffma2(cwr[2 * kk + 1], hv.y, gr[r]);
                    gz[r] = ffma2(cwz[2 * kk], hv.x, gz[r]); gz[r] = ffma2(cwz[2 * kk + 1], hv.y, gz[r]);
                    gn[r] = ffma2(cwn[2 * kk], hv.x, gn[r]); gn[r] = ffma2(cwn[2 * kk + 1], hv.y, gn[r]);
                }
            }
#pragma unroll
            for (int r = 0; r < 4; r++) {
                float xr = g0[r * 96 + lane]      + g1[r * 96 + lane];
                float xz = g0[r * 96 + 32 + lane] + g1[r * 96 + 32 + lane];
                float xn = g0[r * 96 + 64 + lane] + g1[r * 96 + 64 + lane];
                float rg = fast_sigmoid(xr + sum2(gr[r]));
                float zg = fast_sigmoid(xz + sum2(gz[r]));
                float ng = fast_tanh(xn + rg * sum2(gn[r]));    // b_hh_n inside r* (torch GRU)
                h0r[r] = ng + zg * (h0r[r] - ng);
            }
            __syncwarp();
#pragma unroll
            for (int r = 0; r < 4; r++) hs0f[r * 32 + lane] = h0r[r];
            __syncwarp();

            // ---- layer 1: both gemms fused (smem weights) ----
            u64 cr[4], cz[4], cn[4], dr[4], dz[4], dn[4];
#pragma unroll
            for (int r = 0; r < 4; r++) {
                cr[r] = pack2(br1i, 0.f); cz[r] = pack2(bz1i, 0.f); cn[r] = pack2(bn1i, 0.f);
                dr[r] = pack2(br1h, 0.f); dz[r] = pack2(bz1h, 0.f); dn[r] = pack2(bn1h, 0.f);
            }
#pragma unroll
            for (int kk = 0; kk < 8; kk++) {
                ulonglong2 ir  = *(const ulonglong2*)(w4ih1 + kk * 96 + lane);
                ulonglong2 iz  = *(const ulonglong2*)(w4ih1 + kk * 96 + 32 + lane);
                ulonglong2 in_ = *(const ulonglong2*)(w4ih1 + kk * 96 + 64 + lane);
                ulonglong2 hr  = *(const ulonglong2*)(w4hh1 + kk * 96 + lane);
                ulonglong2 hz  = *(const ulonglong2*)(w4hh1 + kk * 96 + 32 + lane);
                ulonglong2 hn  = *(const ulonglong2*)(w4hh1 + kk * 96 + 64 + lane);
#pragma unroll
                for (int r = 0; r < 4; r++) {
                    ulonglong2 h0v = *(const ulonglong2*)(h04 + r * 8 + kk);
                    ulonglong2 h1v = *(const ulonglong2*)(h14 + r * 8 + kk);
                    cr[r] = ffma2(ir.x,  h0v.x, cr[r]); cr[r] = ffma2(ir.y,  h0v.y, cr[r]);
                    cz[r] = ffma2(iz.x,  h0v.x, cz[r]); cz[r] = ffma2(iz.y,  h0v.y, cz[r]);
                    cn[r] = ffma2(in_.x, h0v.x, cn[r]); cn[r] = ffma2(in_.y, h0v.y, cn[r]);
                    dr[r] = ffma2(hr.x,  h1v.x, dr[r]); dr[r] = ffma2(hr.y,  h1v.y, dr[r]);
                    dz[r] = ffma2(hz.x,  h1v.x, dz[r]); dz[r] = ffma2(hz.y,  h1v.y, dz[r]);
                    dn[r] = ffma2(hn.x,  h1v.x, dn[r]); dn[r] = ffma2(hn.y,  h1v.y, dn[r]);
                }
            }
#pragma unroll
            for (int r = 0; r < 4; r++) {
                float rg = fast_sigmoid(sum2(cr[r]) + sum2(dr[r]));
                float zg = fast_sigmoid(sum2(cz[r]) + sum2(dz[r]));
                float ng = fast_tanh(sum2(cn[r]) + rg * sum2(dn[r]));
                h1r[r] = ng + zg * (h1r[r] - ng);
            }
            __syncwarp();
#pragma unroll
            for (int r = 0; r < 4; r++) hs1f[r * 32 + lane] = h1r[r];
            __syncwarp();
        }

        // ---- outputs: y [B], hidden [2,B,H] ----
#pragma unroll
        for (int r = 0; r < 4; r++) {
            int row = rowbase16 + warp * 4 + r;
            out[BB + row * HH + lane] = h0r[r];
            out[BB + BB * HH + row * HH + lane] = h1r[r];
            float p = h1r[r] * wc;
#pragma unroll
            for (int off = 16; off; off >>= 1) p += __shfl_xor_sync(0xffffffffu, p, off);
            if (lane == 0) out[row] = fast_sigmoid(p + bc);
        }
    } else {
        // ================= producer: layer-0 input gemm, 1 step ahead =================
        const int p  = warp - 4;
        const int rg = (p & 1) * 8;          // 8-row group within block
        const int kh = p >> 1;               // K-half of D=64

        // W_ih0 K-half fully register-resident
        u64 pwr[16], pwz[16], pwn[16];
#pragma unroll
        for (int i = 0; i < 8; i++) {
            ulonglong2 a = *(const ulonglong2*)(wih0 + lane * 64        + kh * 32 + i * 4);
            ulonglong2 b = *(const ulonglong2*)(wih0 + (32 + lane) * 64 + kh * 32 + i * 4);
            ulonglong2 c = *(const ulonglong2*)(wih0 + (64 + lane) * 64 + kh * 32 + i * 4);
            pwr[2 * i] = a.x; pwr[2 * i + 1] = a.y;
            pwz[2 * i] = b.x; pwz[2 * i + 1] = b.y;
            pwn[2 * i] = c.x; pwn[2 * i + 1] = c.y;
        }
        float b_r = 0.f, b_z = 0.f, b_n = 0.f;
        if (kh == 0) { b_r = bih0[lane]; b_z = bih0[32 + lane]; b_n = bih0[64 + lane]; }

        float4* xsw = xs + p * 64;           // [8 rows][8 f4] K-half slice staging
        const int s0 = lane, s1 = lane + 32;
        const float* xg0 = x + (size_t)(rowbase16 + rg + (s0 >> 3)) * TT * DD + kh * 32 + (s0 & 7) * 4;
        const float* xg1 = x + (size_t)(rowbase16 + rg + (s1 >> 3)) * TT * DD + kh * 32 + (s1 & 7) * 4;
        float4* xst0 = xsw + s0;
        float4* xst1 = xsw + s1;

        float4 xb0 = *(const float4*)xg0;    // prefetch t=0
        float4 xb1 = *(const float4*)xg1;
        xg0 += DD; xg1 += DD;

        float* gxbase = gxs + kh * 1536 + rg * 96;   // + slot*3072 + r*96

        for (int t = 0; t < TT; t++) {
            *xst0 = xb0;
            *xst1 = xb1;
            __syncwarp();
            if (t + 1 < TT) {
                xb0 = *(const float4*)xg0; xb1 = *(const float4*)xg1;
                xg0 += DD; xg1 += DD;
            }

            u64 ar[8], az[8], an[8];
#pragma unroll
            for (int r = 0; r < 8; r++) {
                ar[r] = pack2(b_r, 0.f); az[r] = pack2(b_z, 0.f); an[r] = pack2(b_n, 0.f);
            }
#pragma unroll
            for (int kk = 0; kk < 8; kk++) {
#pragma unroll
                for (int r = 0; r < 8; r++) {
                    ulonglong2 xv = *(const ulonglong2*)(xsw + r * 8 + kk);
                    ar[r] = ffma2(pwr[2 * kk], xv.x, ar[r]); ar[r] = ffma2(pwr[2 * kk + 1], xv.y, ar[r]);
                    az[r] = ffma2(pwz[2 * kk], xv.x, az[r]); az[r] = ffma2(pwz[2 * kk + 1], xv.y, az[r]);
                    an[r] = ffma2(pwn[2 * kk], xv.x, an[r]); an[r] = ffma2(pwn[2 * kk + 1], xv.y, an[r]);
                }
            }
            float* gout = gxbase + (t & 1) * 3072;
#pragma unroll
            for (int r = 0; r < 8; r++) {
                gout[r * 96 + lane]      = sum2(ar[r]);
                gout[r * 96 + 32 + lane] = sum2(az[r]);
                gout[r * 96 + 64 + lane] = sum2(an[r]);
            }
            BAR_ALL();                        // publish slot t
        }
    }
}

extern "C" void kernel_launch(void* const* d_in, const int* in_sizes, int n_in,
                              void* d_out, int out_size) {
    (void)in_sizes; (void)n_in; (void)out_size;
    const float* x    = (const float*)d_in[0];
    const float* wih0 = (const float*)d_in[1];
    const float* whh0 = (const float*)d_in[2];
    const float* bih0 = (const float*)d_in[3];
    const float* bhh0 = (const float*)d_in[4];
    const float* wih1 = (const float*)d_in[5];
    const float* whh1 = (const float*)d_in[6];
    const float* bih1 = (const float*)d_in[7];
    const float* bhh1 = (const float*)d_in[8];
    const float* wcls = (const float*)d_in[9];
    const float* bcls = (const float*)d_in[10];
    float* out = (float*)d_out;

    const int smem_bytes = 3584 * 16;   // 57,344 B dynamic shared
    cudaFuncSetAttribute(gru2_kernel, cudaFuncAttributeMaxDynamicSharedMemorySize, smem_bytes);
    gru2_kernel<<<128, 256, smem_bytes>>>(x, wih0, whh0, bih0, bhh0,
                                          wih1, whh1, bih1, bhh1, wcls, bcls, out);
}